// round 16
// baseline (speedup 1.0000x reference)
#include <cuda_runtime.h>
#include <cuda.h>
#include <cuda_fp16.h>
#include <math.h>
#include <stdint.h>

// Problem constants
constexpr int BATCH = 2, SEQ = 2048, HID = 2048;
constexpr int NHEADS = 16, GRP = 4, HDIM = 128;
constexpr int MROWS = BATCH * SEQ;        // 4096
constexpr int KVDIM = GRP * HDIM;         // 512

// ---------------------------------------------------------------------------
// Device-global scratch (pure fp16)
// ---------------------------------------------------------------------------
__device__ __align__(128) __half g_X[MROWS * HID];
__device__ __align__(128) __half g_Q[MROWS * HID];
__device__ __align__(128) __half g_K[MROWS * KVDIM];
__device__ __align__(128) __half g_V[MROWS * KVDIM];
__device__ __align__(128) __half g_AO[MROWS * HID];
// Transposed weights, [N][K] K-major
__device__ __align__(128) __half g_WqT[HID * HID];
__device__ __align__(128) __half g_WkT[KVDIM * HID];
__device__ __align__(128) __half g_WvT[KVDIM * HID];
__device__ __align__(128) __half g_WoT[HID * HID];

// ---------------------------------------------------------------------------
// Helpers
// ---------------------------------------------------------------------------
__device__ __forceinline__ uint32_t smem_u32(const void* p) {
    uint32_t a;
    asm("{ .reg .u64 t; cvta.to.shared.u64 t, %1; cvt.u32.u64 %0, t; }"
        : "=r"(a) : "l"(p));
    return a;
}
__device__ __forceinline__ void mma_f16(float* c, const uint32_t* a, const uint32_t* b) {
    asm volatile("mma.sync.aligned.m16n8k16.row.col.f32.f16.f16.f32 "
                 "{%0,%1,%2,%3}, {%4,%5,%6,%7}, {%8,%9}, {%0,%1,%2,%3};"
                 : "+f"(c[0]), "+f"(c[1]), "+f"(c[2]), "+f"(c[3])
                 : "r"(a[0]), "r"(a[1]), "r"(a[2]), "r"(a[3]),
                   "r"(b[0]), "r"(b[1]));
}
#define LDMX4(r0, r1, r2, r3, addr) \
    asm volatile("ldmatrix.sync.aligned.m8n8.x4.shared.b16 {%0,%1,%2,%3}, [%4];" \
                 : "=r"(r0), "=r"(r1), "=r"(r2), "=r"(r3) : "r"(addr))
#define LDMX4T(r0, r1, r2, r3, addr) \
    asm volatile("ldmatrix.sync.aligned.m8n8.x4.trans.shared.b16 {%0,%1,%2,%3}, [%4];" \
                 : "=r"(r0), "=r"(r1), "=r"(r2), "=r"(r3) : "r"(addr))

__device__ __forceinline__ uint32_t packh(float x, float y) {
    __half2 t = __floats2half2_rn(x, y);
    return *(uint32_t*)&t;
}

#define MBAR_INIT(addr, cnt) \
    asm volatile("mbarrier.init.shared.b64 [%0], %1;" :: "r"(addr), "r"(cnt) : "memory")
#define EXPECT_TX(mbar, bytes) \
    asm volatile("mbarrier.arrive.expect_tx.shared.b64 _, [%0], %1;" \
                 :: "r"(mbar), "r"(bytes) : "memory")
#define MBAR_WAIT(addr, parity) do {                                            \
    uint32_t _m = (addr), _p = (parity), _d;                                    \
    asm volatile("{ .reg .pred p;"                                              \
        " mbarrier.try_wait.parity.acquire.cta.shared::cta.b64 p, [%1], %2;"    \
        " selp.b32 %0, 1, 0, p; }" : "=r"(_d) : "r"(_m), "r"(_p) : "memory");   \
    if (!_d) {                                                                  \
        asm volatile("{ .reg .pred P1;"                                         \
            "W%=: mbarrier.try_wait.parity.acquire.cta.shared::cta.b64 P1, [%0], %1, 0x989680;" \
            " @P1 bra.uni D%=; bra.uni W%=; D%=: }"                             \
            :: "r"(_m), "r"(_p) : "memory");                                    \
    }                                                                           \
} while (0)

__device__ __forceinline__ void tma2d(uint32_t saddr, const CUtensorMap* tm,
                                      int x, int y, uint32_t mbar) {
    asm volatile(
        "cp.async.bulk.tensor.2d.shared::cta.global.tile.mbarrier::complete_tx::bytes "
        "[%0], [%1, {%2, %3}], [%4];"
        :: "r"(saddr), "l"(tm), "r"(x), "r"(y), "r"(mbar) : "memory");
}

// ---------------------------------------------------------------------------
// Convert fp32 -> fp16
// ---------------------------------------------------------------------------
__global__ __launch_bounds__(256)
void convert_kernel(const float* __restrict__ x, __half* __restrict__ o, int n4)
{
    int i = blockIdx.x * blockDim.x + threadIdx.x;
    if (i >= n4) return;
    float4 v = ((const float4*)x)[i];
    ((__half2*)o)[i * 2 + 0] = __floats2half2_rn(v.x, v.y);
    ((__half2*)o)[i * 2 + 1] = __floats2half2_rn(v.z, v.w);
}

// ---------------------------------------------------------------------------
// Fused transpose of all 4 weights
// ---------------------------------------------------------------------------
__global__ __launch_bounds__(256)
void transpose_all_kernel(const float* __restrict__ Wq, __half* __restrict__ TQ,
                          const float* __restrict__ Wk, __half* __restrict__ TK,
                          const float* __restrict__ Wv, __half* __restrict__ TV,
                          const float* __restrict__ Wo, __half* __restrict__ TO)
{
    const int z = blockIdx.z;
    const int N = (z == 1 || z == 2) ? KVDIM : HID;
    if (blockIdx.x * 32 >= N) return;
    const float* W = (z == 0) ? Wq : (z == 1) ? Wk : (z == 2) ? Wv : Wo;
    __half* T = (z == 0) ? TQ : (z == 1) ? TK : (z == 2) ? TV : TO;
    const int K = HID;

    __shared__ float tile[32][33];
    int n0 = blockIdx.x * 32, k0 = blockIdx.y * 32;
    int tx = threadIdx.x & 31, ty = threadIdx.x >> 5;
    for (int j = ty; j < 32; j += 8)
        tile[j][tx] = W[(size_t)(k0 + j) * N + n0 + tx];
    __syncthreads();
    for (int j = ty; j < 32; j += 8)
        T[(size_t)(n0 + j) * K + k0 + tx] = __float2half_rn(tile[tx][j]);
}

// ---------------------------------------------------------------------------
// TMA GEMM body (unchanged from round 15)
// ---------------------------------------------------------------------------
constexpr int TTILE = 128 * 128;
constexpr int OFF_BAR = 4 * TTILE;
constexpr int GEMM_SMEM = OFF_BAR + 64;

template <bool HALF_OUT>
__device__ __forceinline__ void gemm_body(
    const CUtensorMap* __restrict__ tmA, const CUtensorMap* __restrict__ tmB,
    const float* __restrict__ bias, float* __restrict__ C,
    __half* __restrict__ Ch,
    int bn, int N, char* smptr)
{
    const uint32_t sbase = smem_u32(smptr);
    const int tid = threadIdx.x;
    const int wid = tid >> 5, lid = tid & 31;
    const int wm = wid >> 2, wn = wid & 3;
    const int m0 = blockIdx.y * 128, n0 = bn * 128;
    const uint32_t mbar = sbase + OFF_BAR;

    if (tid == 0) {
        MBAR_INIT(mbar, 1);
        MBAR_INIT(mbar + 8, 1);
    }
    __syncthreads();

    if (tid == 0) {
        EXPECT_TX(mbar, 2 * TTILE);
        tma2d(sbase + 0 * TTILE, tmA, 0, m0, mbar);
        tma2d(sbase + 1 * TTILE, tmB, 0, n0, mbar);
        EXPECT_TX(mbar + 8, 2 * TTILE);
        tma2d(sbase + 2 * TTILE, tmA, 64, m0, mbar + 8);
        tma2d(sbase + 3 * TTILE, tmB, 64, n0, mbar + 8);
    }

    float acc[4][4][4];
#pragma unroll
    for (int mt = 0; mt < 4; mt++)
#pragma unroll
        for (int nt = 0; nt < 4; nt++)
#pragma unroll
            for (int j = 0; j < 4; j++) acc[mt][nt][j] = 0.f;

    const int laneRow = (lid & 7) + ((lid >> 3) & 1) * 8;
    const int cl = lid >> 4;
    const uint32_t xorv = (uint32_t)(lid & 7) << 4;

    uint32_t ph0 = 0, ph1 = 0;
    const int nch = HID / 64;

    for (int ch = 0; ch < nch; ch++) {
        const int buf = ch & 1;
        if (buf == 0) { MBAR_WAIT(mbar, ph0); ph0 ^= 1; }
        else          { MBAR_WAIT(mbar + 8, ph1); ph1 ^= 1; }

        const uint32_t Ab = sbase + (uint32_t)(buf * 2 + 0) * TTILE
                          + (wm * 64 + laneRow) * 128;
        const uint32_t Bb = sbase + (uint32_t)(buf * 2 + 1) * TTILE
                          + (wn * 32 + laneRow) * 128;

#pragma unroll
        for (int ks = 0; ks < 4; ks++) {
            const uint32_t cb = ((uint32_t)(ks * 2 + cl) << 4) ^ xorv;
            uint32_t a[4][4], b[4][2];
#pragma unroll
            for (int mt = 0; mt < 4; mt++)
                LDMX4(a[mt][0], a[mt][1], a[mt][2], a[mt][3],
                      Ab + mt * 16 * 128 + cb);
#pragma unroll
            for (int j = 0; j < 2; j++) {
                uint32_t t0, t1, t2, t3;
                LDMX4(t0, t1, t2, t3, Bb + j * 16 * 128 + cb);
                b[2 * j][0] = t0; b[2 * j][1] = t2;
                b[2 * j + 1][0] = t1; b[2 * j + 1][1] = t3;
            }
#pragma unroll
            for (int mt = 0; mt < 4; mt++)
#pragma unroll
                for (int nt = 0; nt < 4; nt++)
                    mma_f16(acc[mt][nt], a[mt], b[nt]);
        }
        __syncthreads();
        if (ch + 2 < nch && tid == 0) {
            const uint32_t mb = (buf == 0) ? mbar : mbar + 8;
            EXPECT_TX(mb, 2 * TTILE);
            tma2d(sbase + (uint32_t)(buf * 2 + 0) * TTILE, tmA, (ch + 2) * 64, m0, mb);
            tma2d(sbase + (uint32_t)(buf * 2 + 1) * TTILE, tmB, (ch + 2) * 64, n0, mb);
        }
    }

    const int rbase = m0 + wm * 64 + (lid >> 2);
    const int cbase = n0 + wn * 32 + (lid & 3) * 2;
#pragma unroll
    for (int mt = 0; mt < 4; mt++) {
#pragma unroll
        for (int nt = 0; nt < 4; nt++) {
            int r = rbase + mt * 16;
            int c = cbase + nt * 8;
            float bx = __ldg(&bias[c]), by = __ldg(&bias[c + 1]);
            float v00 = acc[mt][nt][0] + bx, v01 = acc[mt][nt][1] + by;
            float v10 = acc[mt][nt][2] + bx, v11 = acc[mt][nt][3] + by;
            if (HALF_OUT) {
                *(__half2*)&Ch[(size_t)r * N + c] = __floats2half2_rn(v00, v01);
                *(__half2*)&Ch[(size_t)(r + 8) * N + c] = __floats2half2_rn(v10, v11);
            } else {
                *(float2*)&C[(size_t)r * N + c] = make_float2(v00, v01);
                *(float2*)&C[(size_t)(r + 8) * N + c] = make_float2(v10, v11);
            }
        }
    }
}

__global__ __launch_bounds__(256, 2)
void mma_gemm_qkv_kernel(const __grid_constant__ CUtensorMap tmA,
                         const __grid_constant__ CUtensorMap tmBQ,
                         const __grid_constant__ CUtensorMap tmBK,
                         const __grid_constant__ CUtensorMap tmBV,
                         const float* __restrict__ biasQ, __half* __restrict__ QC,
                         const float* __restrict__ biasK, __half* __restrict__ KC,
                         const float* __restrict__ biasV, __half* __restrict__ VC)
{
    extern __shared__ char smg[];
    const int bx = blockIdx.x;
    if (bx < 16)
        gemm_body<true>(&tmA, &tmBQ, biasQ, nullptr, QC, bx, HID, smg);
    else if (bx < 20)
        gemm_body<true>(&tmA, &tmBK, biasK, nullptr, KC, bx - 16, KVDIM, smg);
    else
        gemm_body<true>(&tmA, &tmBV, biasV, nullptr, VC, bx - 20, KVDIM, smg);
}

__global__ __launch_bounds__(256, 2)
void mma_gemm_o_kernel(const __grid_constant__ CUtensorMap tmA,
                       const __grid_constant__ CUtensorMap tmB,
                       const float* __restrict__ bias,
                       float* __restrict__ C)
{
    extern __shared__ char smg[];
    gemm_body<false>(&tmA, &tmB, bias, C, nullptr, blockIdx.x, HID, smg);
}

// ---------------------------------------------------------------------------
// TMA flash attention, QT=128, 8 warps / 256 threads, 2 CTAs/SM.
// Q: 2 SW128 halves of 128 rows. KV: double-buffered, 2 halves each of 64 rows.
// Fully-masked warps skip compute but keep barrier participation.
// ---------------------------------------------------------------------------
constexpr int FQH = 16384;                    // Q half: 128 rows x 128 B
constexpr int FH  = 8192;                     // K/V half: 64 rows x 128 B
constexpr int F_OFF_Q  = 0;                   // 2 halves = 32768
constexpr int F_OFF_KV = 2 * FQH;             // per buf: K0,K1,V0,V1 = 32768
constexpr int F_KVBUF  = 4 * FH;
constexpr int F_OFF_BAR = F_OFF_KV + 2 * F_KVBUF;   // 98304
constexpr int FLASH_SMEM = F_OFF_BAR + 64;          // 98368
constexpr float SM_SCALE = 0.08838834764831845f;

__global__ __launch_bounds__(256, 2)
void flash_mma_kernel(const __grid_constant__ CUtensorMap tmQ,
                      const __grid_constant__ CUtensorMap tmK,
                      const __grid_constant__ CUtensorMap tmV,
                      __half* __restrict__ O)
{
    extern __shared__ __half shb[];
    const uint32_t sb = smem_u32(shb);
    const int tid = threadIdx.x;
    const int w = tid >> 5, lid = tid & 31;
    const int rq = lid >> 2, cq = lid & 3;
    const int qt = gridDim.x - 1 - blockIdx.x;     // reversed: big work first
    const int h = blockIdx.y, b = blockIdx.z;
    const int g = h >> 2;
    const int q0 = qt * 128;
    const uint32_t qbar = sb + F_OFF_BAR;
    const uint32_t kbar = qbar + 16;

    if (tid == 0) {
        MBAR_INIT(qbar, 1);
        MBAR_INIT(kbar, 1);
        MBAR_INIT(kbar + 8, 1);
    }
    __syncthreads();

    const int nkt = 2 * qt + 2;

    auto issue_kv = [&](int kt) {
        const uint32_t bb = sb + F_OFF_KV + (uint32_t)(kt & 1) * F_KVBUF;
        const uint32_t mb = kbar + (uint32_t)(kt & 1) * 8;
        const int y = b * SEQ + kt * 64;
        EXPECT_TX(mb, 4 * FH);
        tma2d(bb + 0 * FH, &tmK, g * HDIM,      y, mb);
        tma2d(bb + 1 * FH, &tmK, g * HDIM + 64, y, mb);
        tma2d(bb + 2 * FH, &tmV, g * HDIM,      y, mb);
        tma2d(bb + 3 * FH, &tmV, g * HDIM + 64, y, mb);
    };

    if (tid == 0) {
        EXPECT_TX(qbar, 2 * FQH);
        tma2d(sb + F_OFF_Q + 0 * FQH, &tmQ, h * HDIM,      b * SEQ + q0, qbar);
        tma2d(sb + F_OFF_Q + 1 * FQH, &tmQ, h * HDIM + 64, b * SEQ + q0, qbar);
        issue_kv(0);
        issue_kv(1);
    }
    MBAR_WAIT(qbar, 0);

    float oacc[16][4];
#pragma unroll
    for (int nt = 0; nt < 16; nt++)
#pragma unroll
        for (int j = 0; j < 4; j++) oacc[nt][j] = 0.f;
    float m0 = -INFINITY, m1 = -INFINITY, l0 = 0.f, l1 = 0.f;

    const int iwmin = q0 + w * 16;
    const int i0 = iwmin + rq;
    const int laneRow = (lid & 7) + ((lid >> 3) & 1) * 8;
    const int cl = lid >> 4;
    const uint32_t xorv = (uint32_t)(lid & 7) << 4;

    uint32_t ph0 = 0, ph1 = 0;

    for (int kt = 0; kt < nkt; kt++) {
        const int k0 = kt * 64;
        if ((kt & 1) == 0) { MBAR_WAIT(kbar, ph0); ph0 ^= 1; }
        else               { MBAR_WAIT(kbar + 8, ph1); ph1 ^= 1; }

        const uint32_t kvb = sb + F_OFF_KV + (uint32_t)(kt & 1) * F_KVBUF;

        if (k0 <= iwmin + 15) {      // warp has unmasked work in this tile
            // ---- S = Q K^T (minimal live fragments) ----
            float sacc[8][4];
#pragma unroll
            for (int nt = 0; nt < 8; nt++)
#pragma unroll
                for (int j = 0; j < 4; j++) sacc[nt][j] = 0.f;

#pragma unroll
            for (int ks = 0; ks < 8; ks++) {
                const uint32_t hk = (uint32_t)(ks >> 2);
                const uint32_t cb = (((uint32_t)(ks & 3) * 32 + cl * 16)) ^ xorv;
                uint32_t a[4];
                LDMX4(a[0], a[1], a[2], a[3],
                      sb + F_OFF_Q + hk * FQH + (w * 16 + laneRow) * 128 + cb);
#pragma unroll
                for (int j = 0; j < 4; j++) {
                    uint32_t t0, t1, t2, t3;
                    LDMX4(t0, t1, t2, t3,
                          kvb + hk * FH + (j * 16 + laneRow) * 128 + cb);
                    uint32_t bA[2] = {t0, t2}, bB[2] = {t1, t3};
                    mma_f16(sacc[2 * j], a, bA);
                    mma_f16(sacc[2 * j + 1], a, bB);
                }
            }

            // ---- scale + causal mask ----
            const bool need_mask = (k0 + 63) > iwmin;
#pragma unroll
            for (int nt = 0; nt < 8; nt++) {
#pragma unroll
                for (int j = 0; j < 4; j++) {
                    float s = sacc[nt][j] * SM_SCALE;
                    if (need_mask) {
                        int jj = k0 + nt * 8 + cq * 2 + (j & 1);
                        int ii = i0 + ((j >> 1) << 3);
                        if (jj > ii) s = -1e30f;
                    }
                    sacc[nt][j] = s;
                }
            }

            // ---- online softmax ----
            float mx0 = -INFINITY, mx1 = -INFINITY;
#pragma unroll
            for (int nt = 0; nt < 8; nt++) {
                mx0 = fmaxf(mx0, fmaxf(sacc[nt][0], sacc[nt][1]));
                mx1 = fmaxf(mx1, fmaxf(sacc[nt][2], sacc[nt][3]));
            }
            mx0 = fmaxf(mx0, __shfl_xor_sync(0xffffffffu, mx0, 1));
            mx0 = fmaxf(mx0, __shfl_xor_sync(0xffffffffu, mx0, 2));
            mx1 = fmaxf(mx1, __shfl_xor_sync(0xffffffffu, mx1, 1));
            mx1 = fmaxf(mx1, __shfl_xor_sync(0xffffffffu, mx1, 2));
            float mn0 = fmaxf(m0, mx0), mn1 = fmaxf(m1, mx1);
            float al0 = __expf(m0 - mn0), al1 = __expf(m1 - mn1);
            m0 = mn0; m1 = mn1;

            float ls0 = 0.f, ls1 = 0.f;
#pragma unroll
            for (int nt = 0; nt < 8; nt++) {
                float p0 = __expf(sacc[nt][0] - mn0);
                float p1 = __expf(sacc[nt][1] - mn0);
                float p2 = __expf(sacc[nt][2] - mn1);
                float p3 = __expf(sacc[nt][3] - mn1);
                ls0 += p0 + p1; ls1 += p2 + p3;
                sacc[nt][0] = p0; sacc[nt][1] = p1;
                sacc[nt][2] = p2; sacc[nt][3] = p3;
            }
            ls0 += __shfl_xor_sync(0xffffffffu, ls0, 1);
            ls0 += __shfl_xor_sync(0xffffffffu, ls0, 2);
            ls1 += __shfl_xor_sync(0xffffffffu, ls1, 1);
            ls1 += __shfl_xor_sync(0xffffffffu, ls1, 2);
            l0 = l0 * al0 + ls0;
            l1 = l1 * al1 + ls1;

#pragma unroll
            for (int nt = 0; nt < 16; nt++) {
                oacc[nt][0] *= al0; oacc[nt][1] *= al0;
                oacc[nt][2] *= al1; oacc[nt][3] *= al1;
            }

            // ---- O += P V (minimal live fragments) ----
            const uint32_t Vb = kvb + 2 * FH;
#pragma unroll
            for (int ks = 0; ks < 4; ks++) {
                uint32_t aP[4];
#pragma unroll
                for (int half = 0; half < 2; half++) {
                    const float* p = sacc[2 * ks + half];
                    aP[2 * half + 0] = packh(p[0], p[1]);
                    aP[2 * half + 1] = packh(p[2], p[3]);
                }
#pragma unroll
                for (int ntp = 0; ntp < 8; ntp++) {
                    const uint32_t hv = (uint32_t)(ntp >> 2) * FH;
                    const uint32_t cb2 = (((uint32_t)(ntp & 3) * 32 + cl * 16)) ^ xorv;
                    uint32_t t0, t1, t2, t3;
                    LDMX4T(t0, t1, t2, t3,
                           Vb + hv + (ks * 16 + (lid & 15)) * 128 + cb2);
                    uint32_t bA[2] = {t0, t1}, bB[2] = {t2, t3};
                    mma_f16(oacc[2 * ntp + 0], aP, bA);
                    mma_f16(oacc[2 * ntp + 1], aP, bB);
                }
            }
        }

        __syncthreads();                 // all reads of this buf done
        if (kt + 2 < nkt && tid == 0)
            issue_kv(kt + 2);
    }

    // ---- normalize + store ----
    const float rl0 = 1.f / l0, rl1 = 1.f / l1;
    const size_t row0 = (size_t)(b * SEQ + q0 + w * 16 + rq);
#pragma unroll
    for (int nt = 0; nt < 16; nt++) {
        int col = h * HDIM + nt * 8 + cq * 2;
        *(__half2*)&O[row0 * HID + col] =
            __floats2half2_rn(oacc[nt][0] * rl0, oacc[nt][1] * rl0);
        *(__half2*)&O[(row0 + 8) * HID + col] =
            __floats2half2_rn(oacc[nt][2] * rl1, oacc[nt][3] * rl1);
    }
}

// ---------------------------------------------------------------------------
// Host: tensor map construction
// ---------------------------------------------------------------------------
typedef CUresult (*PFN_tmenc)(
    CUtensorMap*, CUtensorMapDataType, cuuint32_t, void*,
    const cuuint64_t*, const cuuint64_t*, const cuuint32_t*, const cuuint32_t*,
    CUtensorMapInterleave, CUtensorMapSwizzle, CUtensorMapL2promotion,
    CUtensorMapFloatOOBfill);

static void make_map(PFN_tmenc enc, CUtensorMap* tm, void* ptr,
                     unsigned long long inner, unsigned long long outer,
                     unsigned boxOuter)
{
    cuuint64_t dims[2] = {inner, outer};
    cuuint64_t strides[1] = {inner * 2};
    cuuint32_t box[2] = {64, boxOuter};
    cuuint32_t estr[2] = {1, 1};
    enc(tm, CU_TENSOR_MAP_DATA_TYPE_FLOAT16, 2, ptr, dims, strides, box, estr,
        CU_TENSOR_MAP_INTERLEAVE_NONE, CU_TENSOR_MAP_SWIZZLE_128B,
        CU_TENSOR_MAP_L2_PROMOTION_L2_128B, CU_TENSOR_MAP_FLOAT_OOB_FILL_NONE);
}

extern "C" void kernel_launch(void* const* d_in, const int* in_sizes, int n_in,
                              void* d_out, int out_size)
{
    const float* x  = (const float*)d_in[0];
    const float* Wq = (const float*)d_in[2];
    const float* bq = (const float*)d_in[3];
    const float* Wk = (const float*)d_in[4];
    const float* bk = (const float*)d_in[5];
    const float* Wv = (const float*)d_in[6];
    const float* bv = (const float*)d_in[7];
    const float* Wo = (const float*)d_in[8];
    const float* bo = (const float*)d_in[9];
    float* out = (float*)d_out;

    __half *X, *Q, *K, *V, *AO, *WqT, *WkT, *WvT, *WoT;
    cudaGetSymbolAddress((void**)&X, g_X);
    cudaGetSymbolAddress((void**)&Q, g_Q);
    cudaGetSymbolAddress((void**)&K, g_K);
    cudaGetSymbolAddress((void**)&V, g_V);
    cudaGetSymbolAddress((void**)&AO, g_AO);
    cudaGetSymbolAddress((void**)&WqT, g_WqT);
    cudaGetSymbolAddress((void**)&WkT, g_WkT);
    cudaGetSymbolAddress((void**)&WvT, g_WvT);
    cudaGetSymbolAddress((void**)&WoT, g_WoT);

    void* fn = nullptr;
    cudaDriverEntryPointQueryResult qr;
    cudaGetDriverEntryPoint("cuTensorMapEncodeTiled", &fn,
                            cudaEnableDefault, &qr);
    PFN_tmenc enc = (PFN_tmenc)fn;

    CUtensorMap tmX, tmWq, tmWk, tmWv, tmAO, tmWo, tmQf, tmKf, tmVf;
    make_map(enc, &tmX,  X,   HID, MROWS, 128);
    make_map(enc, &tmWq, WqT, HID, HID,   128);
    make_map(enc, &tmWk, WkT, HID, KVDIM, 128);
    make_map(enc, &tmWv, WvT, HID, KVDIM, 128);
    make_map(enc, &tmAO, AO,  HID, MROWS, 128);
    make_map(enc, &tmWo, WoT, HID, HID,   128);
    make_map(enc, &tmQf, Q,   HID,   MROWS, 128);
    make_map(enc, &tmKf, K,   KVDIM, MROWS, 64);
    make_map(enc, &tmVf, V,   KVDIM, MROWS, 64);

    cudaFuncSetAttribute(mma_gemm_qkv_kernel,
                         cudaFuncAttributeMaxDynamicSharedMemorySize, GEMM_SMEM);
    cudaFuncSetAttribute(mma_gemm_o_kernel,
                         cudaFuncAttributeMaxDynamicSharedMemorySize, GEMM_SMEM);
    cudaFuncSetAttribute(flash_mma_kernel,
                         cudaFuncAttributeMaxDynamicSharedMemorySize, FLASH_SMEM);

    // 1) prep
    convert_kernel<<<(MROWS * HID / 4 + 255) / 256, 256>>>(x, X, MROWS * HID / 4);
    transpose_all_kernel<<<dim3(HID / 32, HID / 32, 4), 256>>>(
        Wq, WqT, Wk, WkT, Wv, WvT, Wo, WoT);

    // 2) fused Q+K+V projection (TMA)
    mma_gemm_qkv_kernel<<<dim3(24, MROWS / 128), 256, GEMM_SMEM>>>(
        tmX, tmWq, tmWk, tmWv, bq, Q, bk, K, bv, V);

    // 3) attention (TMA, 128-row CTAs, 8 warps)
    flash_mma_kernel<<<dim3(SEQ / 128, NHEADS, BATCH), 256, FLASH_SMEM>>>(
        tmQf, tmKf, tmVf, AO);

    // 4) output projection (TMA)
    mma_gemm_o_kernel<<<dim3(HID / 128, MROWS / 128), 256, GEMM_SMEM>>>(
        tmAO, tmWo, bo, out);
}

// round 17
// speedup vs baseline: 1.0483x; 1.0483x over previous
#include <cuda_runtime.h>
#include <cuda.h>
#include <cuda_fp16.h>
#include <math.h>
#include <stdint.h>

// Problem constants
constexpr int BATCH = 2, SEQ = 2048, HID = 2048;
constexpr int NHEADS = 16, GRP = 4, HDIM = 128;
constexpr int MROWS = BATCH * SEQ;        // 4096
constexpr int KVDIM = GRP * HDIM;         // 512

// ---------------------------------------------------------------------------
// Device-global scratch (pure fp16)
// ---------------------------------------------------------------------------
__device__ __align__(128) __half g_X[MROWS * HID];
__device__ __align__(128) __half g_Q[MROWS * HID];
__device__ __align__(128) __half g_K[MROWS * KVDIM];
__device__ __align__(128) __half g_V[MROWS * KVDIM];
__device__ __align__(128) __half g_AO[MROWS * HID];
// Transposed weights, [N][K] K-major
__device__ __align__(128) __half g_WqT[HID * HID];
__device__ __align__(128) __half g_WkT[KVDIM * HID];
__device__ __align__(128) __half g_WvT[KVDIM * HID];
__device__ __align__(128) __half g_WoT[HID * HID];

// ---------------------------------------------------------------------------
// Helpers
// ---------------------------------------------------------------------------
__device__ __forceinline__ uint32_t smem_u32(const void* p) {
    uint32_t a;
    asm("{ .reg .u64 t; cvta.to.shared.u64 t, %1; cvt.u32.u64 %0, t; }"
        : "=r"(a) : "l"(p));
    return a;
}
__device__ __forceinline__ void mma_f16(float* c, const uint32_t* a, const uint32_t* b) {
    asm volatile("mma.sync.aligned.m16n8k16.row.col.f32.f16.f16.f32 "
                 "{%0,%1,%2,%3}, {%4,%5,%6,%7}, {%8,%9}, {%0,%1,%2,%3};"
                 : "+f"(c[0]), "+f"(c[1]), "+f"(c[2]), "+f"(c[3])
                 : "r"(a[0]), "r"(a[1]), "r"(a[2]), "r"(a[3]),
                   "r"(b[0]), "r"(b[1]));
}
#define LDMX4(r0, r1, r2, r3, addr) \
    asm volatile("ldmatrix.sync.aligned.m8n8.x4.shared.b16 {%0,%1,%2,%3}, [%4];" \
                 : "=r"(r0), "=r"(r1), "=r"(r2), "=r"(r3) : "r"(addr))
#define LDMX4T(r0, r1, r2, r3, addr) \
    asm volatile("ldmatrix.sync.aligned.m8n8.x4.trans.shared.b16 {%0,%1,%2,%3}, [%4];" \
                 : "=r"(r0), "=r"(r1), "=r"(r2), "=r"(r3) : "r"(addr))

__device__ __forceinline__ uint32_t packh(float x, float y) {
    __half2 t = __floats2half2_rn(x, y);
    return *(uint32_t*)&t;
}

#define MBAR_INIT(addr, cnt) \
    asm volatile("mbarrier.init.shared.b64 [%0], %1;" :: "r"(addr), "r"(cnt) : "memory")
#define EXPECT_TX(mbar, bytes) \
    asm volatile("mbarrier.arrive.expect_tx.shared.b64 _, [%0], %1;" \
                 :: "r"(mbar), "r"(bytes) : "memory")
#define MBAR_WAIT(addr, parity) do {                                            \
    uint32_t _m = (addr), _p = (parity), _d;                                    \
    asm volatile("{ .reg .pred p;"                                              \
        " mbarrier.try_wait.parity.acquire.cta.shared::cta.b64 p, [%1], %2;"    \
        " selp.b32 %0, 1, 0, p; }" : "=r"(_d) : "r"(_m), "r"(_p) : "memory");   \
    if (!_d) {                                                                  \
        asm volatile("{ .reg .pred P1;"                                         \
            "W%=: mbarrier.try_wait.parity.acquire.cta.shared::cta.b64 P1, [%0], %1, 0x989680;" \
            " @P1 bra.uni D%=; bra.uni W%=; D%=: }"                             \
            :: "r"(_m), "r"(_p) : "memory");                                    \
    }                                                                           \
} while (0)

__device__ __forceinline__ void tma2d(uint32_t saddr, const CUtensorMap* tm,
                                      int x, int y, uint32_t mbar) {
    asm volatile(
        "cp.async.bulk.tensor.2d.shared::cta.global.tile.mbarrier::complete_tx::bytes "
        "[%0], [%1, {%2, %3}], [%4];"
        :: "r"(saddr), "l"(tm), "r"(x), "r"(y), "r"(mbar) : "memory");
}

// ---------------------------------------------------------------------------
// Convert fp32 -> fp16
// ---------------------------------------------------------------------------
__global__ __launch_bounds__(256)
void convert_kernel(const float* __restrict__ x, __half* __restrict__ o, int n4)
{
    int i = blockIdx.x * blockDim.x + threadIdx.x;
    if (i >= n4) return;
    float4 v = ((const float4*)x)[i];
    ((__half2*)o)[i * 2 + 0] = __floats2half2_rn(v.x, v.y);
    ((__half2*)o)[i * 2 + 1] = __floats2half2_rn(v.z, v.w);
}

// ---------------------------------------------------------------------------
// Fused transpose of all 4 weights
// ---------------------------------------------------------------------------
__global__ __launch_bounds__(256)
void transpose_all_kernel(const float* __restrict__ Wq, __half* __restrict__ TQ,
                          const float* __restrict__ Wk, __half* __restrict__ TK,
                          const float* __restrict__ Wv, __half* __restrict__ TV,
                          const float* __restrict__ Wo, __half* __restrict__ TO)
{
    const int z = blockIdx.z;
    const int N = (z == 1 || z == 2) ? KVDIM : HID;
    if (blockIdx.x * 32 >= N) return;
    const float* W = (z == 0) ? Wq : (z == 1) ? Wk : (z == 2) ? Wv : Wo;
    __half* T = (z == 0) ? TQ : (z == 1) ? TK : (z == 2) ? TV : TO;
    const int K = HID;

    __shared__ float tile[32][33];
    int n0 = blockIdx.x * 32, k0 = blockIdx.y * 32;
    int tx = threadIdx.x & 31, ty = threadIdx.x >> 5;
    for (int j = ty; j < 32; j += 8)
        tile[j][tx] = W[(size_t)(k0 + j) * N + n0 + tx];
    __syncthreads();
    for (int j = ty; j < 32; j += 8)
        T[(size_t)(n0 + j) * K + k0 + tx] = __float2half_rn(tile[tx][j]);
}

// ---------------------------------------------------------------------------
// TMA GEMM body: 3-stage pipeline (6 tiles), 128x128 CTA tile, BK=64.
// ---------------------------------------------------------------------------
constexpr int TTILE = 128 * 128;
constexpr int OFF_BAR = 6 * TTILE;          // 98304
constexpr int GEMM_SMEM = OFF_BAR + 64;     // 98368

template <bool HALF_OUT>
__device__ __forceinline__ void gemm_body(
    const CUtensorMap* __restrict__ tmA, const CUtensorMap* __restrict__ tmB,
    const float* __restrict__ bias, float* __restrict__ C,
    __half* __restrict__ Ch,
    int bn, int N, char* smptr)
{
    const uint32_t sbase = smem_u32(smptr);
    const int tid = threadIdx.x;
    const int wid = tid >> 5, lid = tid & 31;
    const int wm = wid >> 2, wn = wid & 3;
    const int m0 = blockIdx.y * 128, n0 = bn * 128;
    const uint32_t mbar = sbase + OFF_BAR;

    if (tid == 0) {
        MBAR_INIT(mbar, 1);
        MBAR_INIT(mbar + 8, 1);
        MBAR_INIT(mbar + 16, 1);
    }
    __syncthreads();

    // prologue: chunks 0,1,2 -> bufs 0,1,2
    if (tid == 0) {
#pragma unroll
        for (int s = 0; s < 3; s++) {
            EXPECT_TX(mbar + s * 8, 2 * TTILE);
            tma2d(sbase + (uint32_t)(s * 2 + 0) * TTILE, tmA, s * 64, m0, mbar + s * 8);
            tma2d(sbase + (uint32_t)(s * 2 + 1) * TTILE, tmB, s * 64, n0, mbar + s * 8);
        }
    }

    float acc[4][4][4];
#pragma unroll
    for (int mt = 0; mt < 4; mt++)
#pragma unroll
        for (int nt = 0; nt < 4; nt++)
#pragma unroll
            for (int j = 0; j < 4; j++) acc[mt][nt][j] = 0.f;

    const int laneRow = (lid & 7) + ((lid >> 3) & 1) * 8;
    const int cl = lid >> 4;
    const uint32_t xorv = (uint32_t)(lid & 7) << 4;

    uint32_t ph[3] = {0, 0, 0};
    const int nch = HID / 64;                  // 32
    int buf = 0;

    for (int ch = 0; ch < nch; ch++) {
        MBAR_WAIT(mbar + buf * 8, ph[buf]);
        ph[buf] ^= 1;

        const uint32_t Ab = sbase + (uint32_t)(buf * 2 + 0) * TTILE
                          + (wm * 64 + laneRow) * 128;
        const uint32_t Bb = sbase + (uint32_t)(buf * 2 + 1) * TTILE
                          + (wn * 32 + laneRow) * 128;

#pragma unroll
        for (int ks = 0; ks < 4; ks++) {
            const uint32_t cb = ((uint32_t)(ks * 2 + cl) << 4) ^ xorv;
            uint32_t a[4][4], b[4][2];
#pragma unroll
            for (int mt = 0; mt < 4; mt++)
                LDMX4(a[mt][0], a[mt][1], a[mt][2], a[mt][3],
                      Ab + mt * 16 * 128 + cb);
#pragma unroll
            for (int j = 0; j < 2; j++) {
                uint32_t t0, t1, t2, t3;
                LDMX4(t0, t1, t2, t3, Bb + j * 16 * 128 + cb);
                b[2 * j][0] = t0; b[2 * j][1] = t2;
                b[2 * j + 1][0] = t1; b[2 * j + 1][1] = t3;
            }
#pragma unroll
            for (int mt = 0; mt < 4; mt++)
#pragma unroll
                for (int nt = 0; nt < 4; nt++)
                    mma_f16(acc[mt][nt], a[mt], b[nt]);
        }
        __syncthreads();                 // all reads of buf done
        if (ch + 3 < nch && tid == 0) {
            const uint32_t mb = mbar + buf * 8;
            EXPECT_TX(mb, 2 * TTILE);
            tma2d(sbase + (uint32_t)(buf * 2 + 0) * TTILE, tmA, (ch + 3) * 64, m0, mb);
            tma2d(sbase + (uint32_t)(buf * 2 + 1) * TTILE, tmB, (ch + 3) * 64, n0, mb);
        }
        buf = (buf == 2) ? 0 : buf + 1;
    }

    const int rbase = m0 + wm * 64 + (lid >> 2);
    const int cbase = n0 + wn * 32 + (lid & 3) * 2;
#pragma unroll
    for (int mt = 0; mt < 4; mt++) {
#pragma unroll
        for (int nt = 0; nt < 4; nt++) {
            int r = rbase + mt * 16;
            int c = cbase + nt * 8;
            float bx = __ldg(&bias[c]), by = __ldg(&bias[c + 1]);
            float v00 = acc[mt][nt][0] + bx, v01 = acc[mt][nt][1] + by;
            float v10 = acc[mt][nt][2] + bx, v11 = acc[mt][nt][3] + by;
            if (HALF_OUT) {
                *(__half2*)&Ch[(size_t)r * N + c] = __floats2half2_rn(v00, v01);
                *(__half2*)&Ch[(size_t)(r + 8) * N + c] = __floats2half2_rn(v10, v11);
            } else {
                *(float2*)&C[(size_t)r * N + c] = make_float2(v00, v01);
                *(float2*)&C[(size_t)(r + 8) * N + c] = make_float2(v10, v11);
            }
        }
    }
}

__global__ __launch_bounds__(256, 2)
void mma_gemm_qkv_kernel(const __grid_constant__ CUtensorMap tmA,
                         const __grid_constant__ CUtensorMap tmBQ,
                         const __grid_constant__ CUtensorMap tmBK,
                         const __grid_constant__ CUtensorMap tmBV,
                         const float* __restrict__ biasQ, __half* __restrict__ QC,
                         const float* __restrict__ biasK, __half* __restrict__ KC,
                         const float* __restrict__ biasV, __half* __restrict__ VC)
{
    extern __shared__ char smg[];
    const int bx = blockIdx.x;
    if (bx < 16)
        gemm_body<true>(&tmA, &tmBQ, biasQ, nullptr, QC, bx, HID, smg);
    else if (bx < 20)
        gemm_body<true>(&tmA, &tmBK, biasK, nullptr, KC, bx - 16, KVDIM, smg);
    else
        gemm_body<true>(&tmA, &tmBV, biasV, nullptr, VC, bx - 20, KVDIM, smg);
}

__global__ __launch_bounds__(256, 2)
void mma_gemm_o_kernel(const __grid_constant__ CUtensorMap tmA,
                       const __grid_constant__ CUtensorMap tmB,
                       const float* __restrict__ bias,
                       float* __restrict__ C)
{
    extern __shared__ char smg[];
    gemm_body<false>(&tmA, &tmB, bias, C, nullptr, blockIdx.x, HID, smg);
}

// ---------------------------------------------------------------------------
// TMA flash attention — exact round-15 version (127 us measured).
// CTA: 64 Q rows, 4 warps / 128 threads, 2 CTAs/SM, double-buffered KV.
// ---------------------------------------------------------------------------
constexpr int FH = 8192;                      // half tile: 64 rows x 128 B
constexpr int F_OFF_Q  = 0;                   // 2 halves = 16384
constexpr int F_OFF_KV = 2 * FH;
constexpr int F_KVBUF  = 4 * FH;
constexpr int F_OFF_BAR = F_OFF_KV + 2 * F_KVBUF;   // 81920
constexpr int FLASH_SMEM = F_OFF_BAR + 64;          // 81984
constexpr float SM_SCALE = 0.08838834764831845f;

__global__ __launch_bounds__(128, 2)
void flash_mma_kernel(const __grid_constant__ CUtensorMap tmQ,
                      const __grid_constant__ CUtensorMap tmK,
                      const __grid_constant__ CUtensorMap tmV,
                      __half* __restrict__ O)
{
    extern __shared__ __half shb[];
    const uint32_t sb = smem_u32(shb);
    const int tid = threadIdx.x;
    const int w = tid >> 5, lid = tid & 31;
    const int rq = lid >> 2, cq = lid & 3;
    const int qt = gridDim.x - 1 - blockIdx.x;
    const int h = blockIdx.y, b = blockIdx.z;
    const int g = h >> 2;
    const int q0 = qt * 64;
    const uint32_t qbar = sb + F_OFF_BAR;
    const uint32_t kbar = qbar + 16;

    if (tid == 0) {
        MBAR_INIT(qbar, 1);
        MBAR_INIT(kbar, 1);
        MBAR_INIT(kbar + 8, 1);
    }
    __syncthreads();

    const int nkt = qt + 1;

    auto issue_kv = [&](int kt) {
        const uint32_t bb = sb + F_OFF_KV + (uint32_t)(kt & 1) * F_KVBUF;
        const uint32_t mb = kbar + (uint32_t)(kt & 1) * 8;
        const int y = b * SEQ + kt * 64;
        EXPECT_TX(mb, 4 * FH);
        tma2d(bb + 0 * FH, &tmK, g * HDIM,      y, mb);
        tma2d(bb + 1 * FH, &tmK, g * HDIM + 64, y, mb);
        tma2d(bb + 2 * FH, &tmV, g * HDIM,      y, mb);
        tma2d(bb + 3 * FH, &tmV, g * HDIM + 64, y, mb);
    };

    if (tid == 0) {
        EXPECT_TX(qbar, 2 * FH);
        tma2d(sb + F_OFF_Q + 0 * FH, &tmQ, h * HDIM,      b * SEQ + q0, qbar);
        tma2d(sb + F_OFF_Q + 1 * FH, &tmQ, h * HDIM + 64, b * SEQ + q0, qbar);
        issue_kv(0);
        if (nkt > 1) issue_kv(1);
    }
    MBAR_WAIT(qbar, 0);

    float oacc[16][4];
#pragma unroll
    for (int nt = 0; nt < 16; nt++)
#pragma unroll
        for (int j = 0; j < 4; j++) oacc[nt][j] = 0.f;
    float m0 = -INFINITY, m1 = -INFINITY, l0 = 0.f, l1 = 0.f;

    const int iwmin = q0 + w * 16;
    const int i0 = iwmin + rq;
    const int laneRow = (lid & 7) + ((lid >> 3) & 1) * 8;
    const int cl = lid >> 4;
    const uint32_t xorv = (uint32_t)(lid & 7) << 4;

    uint32_t ph0 = 0, ph1 = 0;

    for (int kt = 0; kt < nkt; kt++) {
        const int k0 = kt * 64;
        if ((kt & 1) == 0) { MBAR_WAIT(kbar, ph0); ph0 ^= 1; }
        else               { MBAR_WAIT(kbar + 8, ph1); ph1 ^= 1; }

        const uint32_t kvb = sb + F_OFF_KV + (uint32_t)(kt & 1) * F_KVBUF;

        // ---- S = Q K^T ----
        float sacc[8][4];
#pragma unroll
        for (int nt = 0; nt < 8; nt++)
#pragma unroll
            for (int j = 0; j < 4; j++) sacc[nt][j] = 0.f;

#pragma unroll
        for (int ks = 0; ks < 8; ks++) {
            const uint32_t hk = (uint32_t)(ks >> 2) * FH;
            const uint32_t cb = (((uint32_t)(ks & 3) * 32 + cl * 16)) ^ xorv;
            uint32_t a[4], bK[8][2];
            LDMX4(a[0], a[1], a[2], a[3],
                  sb + F_OFF_Q + hk + (w * 16 + laneRow) * 128 + cb);
#pragma unroll
            for (int j = 0; j < 4; j++) {
                uint32_t t0, t1, t2, t3;
                LDMX4(t0, t1, t2, t3,
                      kvb + hk + (j * 16 + laneRow) * 128 + cb);
                bK[2 * j][0] = t0; bK[2 * j][1] = t2;
                bK[2 * j + 1][0] = t1; bK[2 * j + 1][1] = t3;
            }
#pragma unroll
            for (int nt = 0; nt < 8; nt++)
                mma_f16(sacc[nt], a, bK[nt]);
        }

        // ---- scale + causal mask ----
        const bool need_mask = (k0 + 63) > iwmin;
#pragma unroll
        for (int nt = 0; nt < 8; nt++) {
#pragma unroll
            for (int j = 0; j < 4; j++) {
                float s = sacc[nt][j] * SM_SCALE;
                if (need_mask) {
                    int jj = k0 + nt * 8 + cq * 2 + (j & 1);
                    int ii = i0 + ((j >> 1) << 3);
                    if (jj > ii) s = -1e30f;
                }
                sacc[nt][j] = s;
            }
        }

        // ---- online softmax ----
        float mx0 = -INFINITY, mx1 = -INFINITY;
#pragma unroll
        for (int nt = 0; nt < 8; nt++) {
            mx0 = fmaxf(mx0, fmaxf(sacc[nt][0], sacc[nt][1]));
            mx1 = fmaxf(mx1, fmaxf(sacc[nt][2], sacc[nt][3]));
        }
        mx0 = fmaxf(mx0, __shfl_xor_sync(0xffffffffu, mx0, 1));
        mx0 = fmaxf(mx0, __shfl_xor_sync(0xffffffffu, mx0, 2));
        mx1 = fmaxf(mx1, __shfl_xor_sync(0xffffffffu, mx1, 1));
        mx1 = fmaxf(mx1, __shfl_xor_sync(0xffffffffu, mx1, 2));
        float mn0 = fmaxf(m0, mx0), mn1 = fmaxf(m1, mx1);
        float al0 = __expf(m0 - mn0), al1 = __expf(m1 - mn1);
        m0 = mn0; m1 = mn1;

        float ls0 = 0.f, ls1 = 0.f;
#pragma unroll
        for (int nt = 0; nt < 8; nt++) {
            float p0 = __expf(sacc[nt][0] - mn0);
            float p1 = __expf(sacc[nt][1] - mn0);
            float p2 = __expf(sacc[nt][2] - mn1);
            float p3 = __expf(sacc[nt][3] - mn1);
            ls0 += p0 + p1; ls1 += p2 + p3;
            sacc[nt][0] = p0; sacc[nt][1] = p1; sacc[nt][2] = p2; sacc[nt][3] = p3;
        }
        ls0 += __shfl_xor_sync(0xffffffffu, ls0, 1);
        ls0 += __shfl_xor_sync(0xffffffffu, ls0, 2);
        ls1 += __shfl_xor_sync(0xffffffffu, ls1, 1);
        ls1 += __shfl_xor_sync(0xffffffffu, ls1, 2);
        l0 = l0 * al0 + ls0;
        l1 = l1 * al1 + ls1;

#pragma unroll
        for (int nt = 0; nt < 16; nt++) {
            oacc[nt][0] *= al0; oacc[nt][1] *= al0;
            oacc[nt][2] *= al1; oacc[nt][3] *= al1;
        }

        // ---- O += P V ----
        const uint32_t Vb = kvb + 2 * FH;
#pragma unroll
        for (int ks = 0; ks < 4; ks++) {
            uint32_t aP[4];
#pragma unroll
            for (int half = 0; half < 2; half++) {
                const float* p = sacc[2 * ks + half];
                aP[2 * half + 0] = packh(p[0], p[1]);
                aP[2 * half + 1] = packh(p[2], p[3]);
            }
            uint32_t bv[8][4];
#pragma unroll
            for (int ntp = 0; ntp < 8; ntp++) {
                const uint32_t hv = (uint32_t)(ntp >> 2) * FH;
                const uint32_t cb2 = (((uint32_t)(ntp & 3) * 32 + cl * 16)) ^ xorv;
                const uint32_t va = Vb + hv + (ks * 16 + (lid & 15)) * 128 + cb2;
                LDMX4T(bv[ntp][0], bv[ntp][1], bv[ntp][2], bv[ntp][3], va);
            }
#pragma unroll
            for (int ntp = 0; ntp < 8; ntp++) {
                mma_f16(oacc[2 * ntp + 0], aP, &bv[ntp][0]);
                mma_f16(oacc[2 * ntp + 1], aP, &bv[ntp][2]);
            }
        }

        __syncthreads();
        if (kt + 2 < nkt && tid == 0)
            issue_kv(kt + 2);
    }

    // ---- normalize + store ----
    const float rl0 = 1.f / l0, rl1 = 1.f / l1;
    const size_t row0 = (size_t)(b * SEQ + q0 + w * 16 + rq);
#pragma unroll
    for (int nt = 0; nt < 16; nt++) {
        int col = h * HDIM + nt * 8 + cq * 2;
        *(__half2*)&O[row0 * HID + col] =
            __floats2half2_rn(oacc[nt][0] * rl0, oacc[nt][1] * rl0);
        *(__half2*)&O[(row0 + 8) * HID + col] =
            __floats2half2_rn(oacc[nt][2] * rl1, oacc[nt][3] * rl1);
    }
}

// ---------------------------------------------------------------------------
// Host: tensor map construction
// ---------------------------------------------------------------------------
typedef CUresult (*PFN_tmenc)(
    CUtensorMap*, CUtensorMapDataType, cuuint32_t, void*,
    const cuuint64_t*, const cuuint64_t*, const cuuint32_t*, const cuuint32_t*,
    CUtensorMapInterleave, CUtensorMapSwizzle, CUtensorMapL2promotion,
    CUtensorMapFloatOOBfill);

static void make_map(PFN_tmenc enc, CUtensorMap* tm, void* ptr,
                     unsigned long long inner, unsigned long long outer,
                     unsigned boxOuter)
{
    cuuint64_t dims[2] = {inner, outer};
    cuuint64_t strides[1] = {inner * 2};
    cuuint32_t box[2] = {64, boxOuter};
    cuuint32_t estr[2] = {1, 1};
    enc(tm, CU_TENSOR_MAP_DATA_TYPE_FLOAT16, 2, ptr, dims, strides, box, estr,
        CU_TENSOR_MAP_INTERLEAVE_NONE, CU_TENSOR_MAP_SWIZZLE_128B,
        CU_TENSOR_MAP_L2_PROMOTION_L2_128B, CU_TENSOR_MAP_FLOAT_OOB_FILL_NONE);
}

extern "C" void kernel_launch(void* const* d_in, const int* in_sizes, int n_in,
                              void* d_out, int out_size)
{
    const float* x  = (const float*)d_in[0];
    const float* Wq = (const float*)d_in[2];
    const float* bq = (const float*)d_in[3];
    const float* Wk = (const float*)d_in[4];
    const float* bk = (const float*)d_in[5];
    const float* Wv = (const float*)d_in[6];
    const float* bv = (const float*)d_in[7];
    const float* Wo = (const float*)d_in[8];
    const float* bo = (const float*)d_in[9];
    float* out = (float*)d_out;

    __half *X, *Q, *K, *V, *AO, *WqT, *WkT, *WvT, *WoT;
    cudaGetSymbolAddress((void**)&X, g_X);
    cudaGetSymbolAddress((void**)&Q, g_Q);
    cudaGetSymbolAddress((void**)&K, g_K);
    cudaGetSymbolAddress((void**)&V, g_V);
    cudaGetSymbolAddress((void**)&AO, g_AO);
    cudaGetSymbolAddress((void**)&WqT, g_WqT);
    cudaGetSymbolAddress((void**)&WkT, g_WkT);
    cudaGetSymbolAddress((void**)&WvT, g_WvT);
    cudaGetSymbolAddress((void**)&WoT, g_WoT);

    void* fn = nullptr;
    cudaDriverEntryPointQueryResult qr;
    cudaGetDriverEntryPoint("cuTensorMapEncodeTiled", &fn,
                            cudaEnableDefault, &qr);
    PFN_tmenc enc = (PFN_tmenc)fn;

    CUtensorMap tmX, tmWq, tmWk, tmWv, tmAO, tmWo, tmQf, tmKf, tmVf;
    make_map(enc, &tmX,  X,   HID, MROWS, 128);
    make_map(enc, &tmWq, WqT, HID, HID,   128);
    make_map(enc, &tmWk, WkT, HID, KVDIM, 128);
    make_map(enc, &tmWv, WvT, HID, KVDIM, 128);
    make_map(enc, &tmAO, AO,  HID, MROWS, 128);
    make_map(enc, &tmWo, WoT, HID, HID,   128);
    make_map(enc, &tmQf, Q,   HID,   MROWS, 64);
    make_map(enc, &tmKf, K,   KVDIM, MROWS, 64);
    make_map(enc, &tmVf, V,   KVDIM, MROWS, 64);

    cudaFuncSetAttribute(mma_gemm_qkv_kernel,
                         cudaFuncAttributeMaxDynamicSharedMemorySize, GEMM_SMEM);
    cudaFuncSetAttribute(mma_gemm_o_kernel,
                         cudaFuncAttributeMaxDynamicSharedMemorySize, GEMM_SMEM);
    cudaFuncSetAttribute(flash_mma_kernel,
                         cudaFuncAttributeMaxDynamicSharedMemorySize, FLASH_SMEM);

    // 1) prep
    convert_kernel<<<(MROWS * HID / 4 + 255) / 256, 256>>>(x, X, MROWS * HID / 4);
    transpose_all_kernel<<<dim3(HID / 32, HID / 32, 4), 256>>>(
        Wq, WqT, Wk, WkT, Wv, WvT, Wo, WoT);

    // 2) fused Q+K+V projection (TMA, 3-stage)
    mma_gemm_qkv_kernel<<<dim3(24, MROWS / 128), 256, GEMM_SMEM>>>(
        tmX, tmWq, tmWk, tmWv, bq, Q, bk, K, bv, V);

    // 3) attention (TMA, round-15 config)
    flash_mma_kernel<<<dim3(SEQ / 64, NHEADS, BATCH), 128, FLASH_SMEM>>>(
        tmQf, tmKf, tmVf, AO);

    // 4) output projection (TMA, 3-stage)
    mma_gemm_o_kernel<<<dim3(HID / 128, MROWS / 128), 256, GEMM_SMEM>>>(
        tmAO, tmWo, bo, out);
}